// round 6
// baseline (speedup 1.0000x reference)
#include <cuda_runtime.h>
#include <math.h>
#include <stdint.h>

#define BATCH 4
#define MPTS  16384
#define NPTS  32768
#define KNN   16
#define CH    64          // channels in = channels out
#define ROWS  (BATCH*NPTS)   // 131072
#define OUTC  131
#define BN_EPS 1e-5f

// ---------------- scratch (static device memory; no allocation) --------------
__device__ float  g_y1[(size_t)ROWS * CH];   // pooled @ W1 + b1
__device__ float  g_y2[(size_t)ROWS * CH];   // skip   @ W2 + b2
__device__ double g_stats[256];              // [sum1|sq1|sum2|sq2] x 64 ch
__device__ float  g_aff[256];                // [a1|d1|a2|d2] x 64 ch
__device__ int    g_odd_nonzero;             // idx dtype detector

// ---------------- init ----------------
__global__ void k_init() {
    g_stats[threadIdx.x] = 0.0;
    if (threadIdx.x == 0) g_odd_nonzero = 0;
}

// Detect whether upsampling_idxs is int64 (little-endian: high words all zero)
// or int32. Checks the first 65536 logical entries -> in bounds for both dtypes.
__global__ void k_detect(const int* __restrict__ idx) {
    int e = (blockIdx.x * 256 + threadIdx.x) * 4;
    int nz = 0;
#pragma unroll
    for (int u = 0; u < 4; ++u) nz |= idx[2 * (e + u) + 1];
    unsigned bal = __ballot_sync(0xffffffffu, nz != 0);
    if ((threadIdx.x & 31) == 0 && bal) atomicOr(&g_odd_nonzero, 1);
}

// ---------------- main fused kernel ----------------
// Warp handles 8 rows. Each lane owns 2 channels (2*lane, 2*lane+1).
// x values live in registers; broadcast over the warp via shuffles.
// W columns register-tiled in chunks of 8 j's from shared memory.
__device__ __forceinline__ void gemm8(const float2* __restrict__ sW,
                                      const float2* x, float2* acc, int lane) {
#pragma unroll
    for (int jc = 0; jc < 8; ++jc) {
        float2 w[8];
#pragma unroll
        for (int jj = 0; jj < 8; ++jj) w[jj] = sW[(jc * 8 + jj) * 32 + lane];
#pragma unroll
        for (int r = 0; r < 8; ++r) {
#pragma unroll
            for (int jj = 0; jj < 8; ++jj) {
                const int j = jc * 8 + jj;
                float xv = __shfl_sync(0xffffffffu, (j & 1) ? x[r].y : x[r].x, j >> 1);
                acc[r].x = fmaf(xv, w[jj].x, acc[r].x);
                acc[r].y = fmaf(xv, w[jj].y, acc[r].y);
            }
        }
    }
}

__global__ void __launch_bounds__(256)
k_main(const float* __restrict__ curr_feat,
       const float* __restrict__ skip_feat,
       const int*   __restrict__ idx,
       const float* __restrict__ W1, const float* __restrict__ b1,
       const float* __restrict__ W2, const float* __restrict__ b2) {
    __shared__ float2 sW1[2048];   // [j][lane] = (W1[j][2l], W1[j][2l+1])
    __shared__ float2 sW2[2048];
    __shared__ float  sred[256];

    const float2* W1v = (const float2*)W1;
    const float2* W2v = (const float2*)W2;
    for (int t = threadIdx.x; t < 2048; t += 256) { sW1[t] = W1v[t]; sW2[t] = W2v[t]; }
    sred[threadIdx.x] = 0.f;
    __syncthreads();

    const int lane = threadIdx.x & 31;
    const int warp = threadIdx.x >> 5;
    const int rowBase = (blockIdx.x * 8 + warp) * 8;
    const bool is64 = (g_odd_nonzero == 0);

    // ---- gather + max-pool over KNN neighbors ----
    float2 x[8];
#pragma unroll
    for (int r = 0; r < 8; ++r) {
        const int row = rowBase + r;
        const int b = row >> 15;           // row / NPTS
        int myidx = 0;
        if (lane < KNN) {
            const int off = row * KNN + lane;
            myidx = is64 ? idx[2 * off] : idx[off];
        }
        const float2* fb = (const float2*)curr_feat + (size_t)b * (MPTS * 32);
        float2 m = make_float2(-__builtin_huge_valf(), -__builtin_huge_valf());
#pragma unroll
        for (int k = 0; k < KNN; ++k) {
            const int id = __shfl_sync(0xffffffffu, myidx, k);
            const float2 v = fb[(size_t)id * 32 + lane];
            m.x = fmaxf(m.x, v.x);
            m.y = fmaxf(m.y, v.y);
        }
        x[r] = m;
    }

    // ---- GEMM1: y1 = pooled @ W1 + b1 ----
    float2 acc[8];
    {
        const float2 bias = ((const float2*)b1)[lane];
#pragma unroll
        for (int r = 0; r < 8; ++r) acc[r] = bias;
    }
    gemm8(sW1, x, acc, lane);

    float2 s1 = make_float2(0.f, 0.f), q1 = make_float2(0.f, 0.f);
#pragma unroll
    for (int r = 0; r < 8; ++r) {
        s1.x += acc[r].x;  s1.y += acc[r].y;
        q1.x = fmaf(acc[r].x, acc[r].x, q1.x);
        q1.y = fmaf(acc[r].y, acc[r].y, q1.y);
        ((float2*)g_y1)[(size_t)(rowBase + r) * 32 + lane] = acc[r];
    }

    // ---- GEMM2: y2 = skip_feat @ W2 + b2 ----
#pragma unroll
    for (int r = 0; r < 8; ++r)
        x[r] = ((const float2*)skip_feat)[(size_t)(rowBase + r) * 32 + lane];
    {
        const float2 bias = ((const float2*)b2)[lane];
#pragma unroll
        for (int r = 0; r < 8; ++r) acc[r] = bias;
    }
    gemm8(sW2, x, acc, lane);

    float2 s2 = make_float2(0.f, 0.f), q2 = make_float2(0.f, 0.f);
#pragma unroll
    for (int r = 0; r < 8; ++r) {
        s2.x += acc[r].x;  s2.y += acc[r].y;
        q2.x = fmaf(acc[r].x, acc[r].x, q2.x);
        q2.y = fmaf(acc[r].y, acc[r].y, q2.y);
        ((float2*)g_y2)[(size_t)(rowBase + r) * 32 + lane] = acc[r];
    }

    // ---- hierarchical stats reduction ----
    const int c0 = 2 * lane;
    atomicAdd(&sred[c0],           s1.x);  atomicAdd(&sred[c0 + 1],       s1.y);
    atomicAdd(&sred[64 + c0],      q1.x);  atomicAdd(&sred[64 + c0 + 1],  q1.y);
    atomicAdd(&sred[128 + c0],     s2.x);  atomicAdd(&sred[128 + c0 + 1], s2.y);
    atomicAdd(&sred[192 + c0],     q2.x);  atomicAdd(&sred[192 + c0 + 1], q2.y);
    __syncthreads();
    atomicAdd(&g_stats[threadIdx.x], (double)sred[threadIdx.x]);
}

// ---------------- BN constant finalize ----------------
__global__ void k_finalize(const float* __restrict__ g1, const float* __restrict__ beta1,
                           const float* __restrict__ g2, const float* __restrict__ beta2) {
    const int t = threadIdx.x;   // 128 threads
    const double inv = 1.0 / (double)ROWS;
    if (t < 64) {
        const double mean = g_stats[t] * inv;
        const double var  = g_stats[64 + t] * inv - mean * mean;
        const float a = g1[t] * rsqrtf((float)var + BN_EPS);
        g_aff[t]      = a;
        g_aff[64 + t] = beta1[t] - (float)mean * a;
    } else {
        const int c = t - 64;
        const double mean = g_stats[128 + c] * inv;
        const double var  = g_stats[192 + c] * inv - mean * mean;
        const float a = g2[c] * rsqrtf((float)var + BN_EPS);
        g_aff[128 + c] = a;
        g_aff[192 + c] = beta2[c] - (float)mean * a;
    }
}

// ---------------- epilogue: normalize + relu + concat ----------------
__global__ void __launch_bounds__(256)
k_epilogue(const float* __restrict__ skip_coords, float* __restrict__ out) {
    const int i = blockIdx.x * 256 + threadIdx.x;
    if (i >= ROWS * OUTC) return;
    const int row = i / OUTC;
    const int p = i - row * OUTC;
    float v;
    if (p < 3) {
        v = skip_coords[(size_t)row * 3 + p];
    } else if (p < 3 + CH) {
        const int c = p - 3;
        v = fmaxf(fmaf(g_y1[(size_t)row * CH + c], g_aff[c], g_aff[64 + c]), 0.f);
    } else {
        const int c = p - 3 - CH;
        v = fmaxf(fmaf(g_y2[(size_t)row * CH + c], g_aff[128 + c], g_aff[192 + c]), 0.f);
    }
    out[i] = v;
}

// ---------------- launch ----------------
extern "C" void kernel_launch(void* const* d_in, const int* in_sizes, int n_in,
                              void* d_out, int out_size) {
    // metadata order:
    // 0 curr_coords (unused), 1 curr_feat, 2 skip_coords, 3 skip_feat,
    // 4 upsampling_idxs, 5 W1, 6 b1, 7 g1, 8 beta1, 9 W2, 10 b2, 11 g2, 12 beta2
    const float* curr_feat   = (const float*)d_in[1];
    const float* skip_coords = (const float*)d_in[2];
    const float* skip_feat   = (const float*)d_in[3];
    const int*   idx         = (const int*)d_in[4];
    const float* W1 = (const float*)d_in[5];
    const float* b1 = (const float*)d_in[6];
    const float* g1 = (const float*)d_in[7];
    const float* be1 = (const float*)d_in[8];
    const float* W2 = (const float*)d_in[9];
    const float* b2 = (const float*)d_in[10];
    const float* g2 = (const float*)d_in[11];
    const float* be2 = (const float*)d_in[12];
    float* out = (float*)d_out;

    k_init<<<1, 256>>>();
    k_detect<<<64, 256>>>(idx);
    k_main<<<ROWS / 64, 256>>>(curr_feat, skip_feat, idx, W1, b1, W2, b2);
    k_finalize<<<1, 128>>>(g1, be1, g2, be2);
    k_epilogue<<<(ROWS * OUTC + 255) / 256, 256>>>(skip_coords, out);
}

// round 9
// speedup vs baseline: 1.1433x; 1.1433x over previous
#include <cuda_runtime.h>
#include <math.h>
#include <stdint.h>

typedef unsigned long long u64;

#define BATCH 4
#define MPTS  16384
#define NPTS  32768
#define KNN   16
#define CH    64
#define ROWS  (BATCH*NPTS)     // 131072
#define OUTC  131
#define BN_EPS 1e-5f

#define WARPS 8
#define PAIRS 16               // row-pairs per warp
#define RPW   (2*PAIRS)        // 32 rows per warp
#define RPB   (WARPS*RPW)      // 256 rows per block
#define GRID_MAIN (ROWS/RPB)   // 512

// dynamic smem: sW (4096 u64, W duplicated), sx (8 warps * 1024 u64), sred (256 f32)
#define SMEM_BYTES ((4096 + 8192) * 8 + 256 * 4)

// ---------------- scratch (static device memory; no allocation) --------------
__device__ float  g_y1[(size_t)ROWS * CH];
__device__ float  g_y2[(size_t)ROWS * CH];
__device__ double g_stats[256];      // [sum1|sq1|sum2|sq2] x 64 ch
__device__ float  g_aff[256];        // [a1|d1|a2|d2] x 64 ch
__device__ int    g_odd_nonzero;     // idx dtype detector (OR-only, idempotent)
__device__ unsigned int g_cnt;       // last-block counter

// ---------------- packed f32x2 helpers ----------------
__device__ __forceinline__ u64 pk(float lo, float hi) {
    u64 r; asm("mov.b64 %0,{%1,%2};" : "=l"(r) : "f"(lo), "f"(hi)); return r;
}
__device__ __forceinline__ void upk(u64 v, float& lo, float& hi) {
    asm("mov.b64 {%0,%1},%2;" : "=f"(lo), "=f"(hi) : "l"(v));
}
__device__ __forceinline__ void fma2(u64& d, u64 a, u64 b) {
    asm("fma.rn.f32x2 %0,%1,%2,%0;" : "+l"(d) : "l"(a), "l"(b));
}
__device__ __forceinline__ void add2(u64& d, u64 a) {
    asm("add.rn.f32x2 %0,%0,%1;" : "+l"(d) : "l"(a));
}

// ---------------- pre: reset + idx dtype detect ----------------
__global__ void k_pre(const int* __restrict__ idx) {
    if (blockIdx.x == 0) {
        g_stats[threadIdx.x] = 0.0;
        if (threadIdx.x == 0) g_cnt = 0u;
    }
    int e = (blockIdx.x * 256 + threadIdx.x) * 4;
    int nz = 0;
#pragma unroll
    for (int u = 0; u < 4; ++u) nz |= idx[2 * (e + u) + 1];
    unsigned bal = __ballot_sync(0xffffffffu, nz != 0);
    if ((threadIdx.x & 31) == 0 && bal) atomicOr(&g_odd_nonzero, 1);
}

// ---------------- gather one row: KNN max-pool, lane owns ch (2l, 2l+1) ------
__device__ __forceinline__ float2 gather_row(const float2* __restrict__ cf,
                                             const int* __restrict__ idx,
                                             int row, int lane, bool is64) {
    const float2* fb = cf + (size_t)(row >> 15) * (MPTS * 32);
    int myidx = 0;
    if (lane < KNN) {
        const int off = row * KNN + lane;
        myidx = is64 ? idx[2 * off] : idx[off];
    }
    float2 m = make_float2(-3.0e38f, -3.0e38f);
#pragma unroll
    for (int k = 0; k < KNN; ++k) {
        const int id = __shfl_sync(0xffffffffu, myidx, k);
        const float2 v = __ldg(&fb[(size_t)id * 32 + lane]);
        m.x = fmaxf(m.x, v.x);
        m.y = fmaxf(m.y, v.y);
    }
    return m;
}

// ---------------- packed-pair GEMM: acc over 16 row-pairs, 2 channels --------
__device__ __forceinline__ void gemm_pairs(const u64* __restrict__ sW,
                                           const u64* __restrict__ sxw,
                                           u64* acc0, u64* acc1, int l2) {
#pragma unroll 1
    for (int k = 0; k < 64; k += 2) {
        ulonglong2 wA = *(const ulonglong2*)(sW + k * 64 + l2);        // dup W[k][c0],W[k][c1]
        ulonglong2 wB = *(const ulonglong2*)(sW + (k + 1) * 64 + l2);
#pragma unroll
        for (int p = 0; p < PAIRS; ++p) {
            ulonglong2 xq = *(const ulonglong2*)(sxw + p * 64 + k);    // x pair k, pair k+1
            fma2(acc0[p], xq.x, wA.x);
            fma2(acc1[p], xq.x, wA.y);
            fma2(acc0[p], xq.y, wB.x);
            fma2(acc1[p], xq.y, wB.y);
        }
    }
}

// ---------------- main fused kernel ----------------
__global__ void __launch_bounds__(256, 2)
k_main(const float* __restrict__ curr_feat,
       const float* __restrict__ skip_feat,
       const int*   __restrict__ idx,
       const float* __restrict__ W1, const float* __restrict__ b1,
       const float* __restrict__ W2, const float* __restrict__ b2,
       const float* __restrict__ g1, const float* __restrict__ be1,
       const float* __restrict__ g2, const float* __restrict__ be2) {
    extern __shared__ u64 dsm[];
    u64*   sW   = dsm;                 // 4096 u64
    u64*   sx   = dsm + 4096;          // 8192 u64
    float* sred = (float*)(dsm + 4096 + 8192);
    __shared__ int slast;

    const int lane = threadIdx.x & 31;
    const int warp = threadIdx.x >> 5;
    const int l2   = 2 * lane;
    const int base = (blockIdx.x * WARPS + warp) * RPW;
    const bool is64 = (g_odd_nonzero == 0);
    u64* sxw = sx + warp * (PAIRS * 64);

    // stage W1 duplicated + zero sred
    for (int t = threadIdx.x; t < 4096; t += 256) { float w = W1[t]; sW[t] = pk(w, w); }
    sred[threadIdx.x] = 0.f;

    // gather + max-pool + pack row pairs into smem
#pragma unroll 1
    for (int p = 0; p < PAIRS; ++p) {
        float2 xa = gather_row((const float2*)curr_feat, idx, base + 2 * p,     lane, is64);
        float2 xb = gather_row((const float2*)curr_feat, idx, base + 2 * p + 1, lane, is64);
        ulonglong2 pr; pr.x = pk(xa.x, xb.x); pr.y = pk(xa.y, xb.y);
        *(ulonglong2*)(sxw + p * 64 + l2) = pr;
    }
    __syncthreads();   // W1 staged + own x visible

    // ---- GEMM1 ----
    u64 acc0[PAIRS], acc1[PAIRS];
    {
        float2 bb = ((const float2*)b1)[lane];
        u64 c0 = pk(bb.x, bb.x), c1 = pk(bb.y, bb.y);
#pragma unroll
        for (int p = 0; p < PAIRS; ++p) { acc0[p] = c0; acc1[p] = c1; }
    }
    gemm_pairs(sW, sxw, acc0, acc1, l2);

    // stats + store y1
    {
        u64 s0 = 0, s1 = 0, q0 = 0, q1 = 0;
#pragma unroll
        for (int p = 0; p < PAIRS; ++p) {
            add2(s0, acc0[p]); add2(s1, acc1[p]);
            fma2(q0, acc0[p], acc0[p]); fma2(q1, acc1[p], acc1[p]);
            float aLo, aHi, bLo, bHi;
            upk(acc0[p], aLo, aHi); upk(acc1[p], bLo, bHi);
            ((float2*)g_y1)[(size_t)(base + 2 * p) * 32 + lane]     = make_float2(aLo, bLo);
            ((float2*)g_y1)[(size_t)(base + 2 * p + 1) * 32 + lane] = make_float2(aHi, bHi);
        }
        float lo, hi;
        upk(s0, lo, hi); atomicAdd(&sred[l2],          lo + hi);
        upk(s1, lo, hi); atomicAdd(&sred[l2 + 1],      lo + hi);
        upk(q0, lo, hi); atomicAdd(&sred[64 + l2],     lo + hi);
        upk(q1, lo, hi); atomicAdd(&sred[64 + l2 + 1], lo + hi);
    }
    __syncthreads();   // everyone done reading W1

    // stage W2 + pack skip_feat pairs
    for (int t = threadIdx.x; t < 4096; t += 256) { float w = W2[t]; sW[t] = pk(w, w); }
#pragma unroll 1
    for (int p = 0; p < PAIRS; ++p) {
        float2 xa = ((const float2*)skip_feat)[(size_t)(base + 2 * p) * 32 + lane];
        float2 xb = ((const float2*)skip_feat)[(size_t)(base + 2 * p + 1) * 32 + lane];
        ulonglong2 pr; pr.x = pk(xa.x, xb.x); pr.y = pk(xa.y, xb.y);
        *(ulonglong2*)(sxw + p * 64 + l2) = pr;
    }
    __syncthreads();

    // ---- GEMM2 ----
    {
        float2 bb = ((const float2*)b2)[lane];
        u64 c0 = pk(bb.x, bb.x), c1 = pk(bb.y, bb.y);
#pragma unroll
        for (int p = 0; p < PAIRS; ++p) { acc0[p] = c0; acc1[p] = c1; }
    }
    gemm_pairs(sW, sxw, acc0, acc1, l2);

    {
        u64 s0 = 0, s1 = 0, q0 = 0, q1 = 0;
#pragma unroll
        for (int p = 0; p < PAIRS; ++p) {
            add2(s0, acc0[p]); add2(s1, acc1[p]);
            fma2(q0, acc0[p], acc0[p]); fma2(q1, acc1[p], acc1[p]);
            float aLo, aHi, bLo, bHi;
            upk(acc0[p], aLo, aHi); upk(acc1[p], bLo, bHi);
            ((float2*)g_y2)[(size_t)(base + 2 * p) * 32 + lane]     = make_float2(aLo, bLo);
            ((float2*)g_y2)[(size_t)(base + 2 * p + 1) * 32 + lane] = make_float2(aHi, bHi);
        }
        float lo, hi;
        upk(s0, lo, hi); atomicAdd(&sred[128 + l2],     lo + hi);
        upk(s1, lo, hi); atomicAdd(&sred[128 + l2 + 1], lo + hi);
        upk(q0, lo, hi); atomicAdd(&sred[192 + l2],     lo + hi);
        upk(q1, lo, hi); atomicAdd(&sred[192 + l2 + 1], lo + hi);
    }
    __syncthreads();

    // global stats + last-block inline finalize
    atomicAdd(&g_stats[threadIdx.x], (double)sred[threadIdx.x]);
    __threadfence();
    __syncthreads();
    if (threadIdx.x == 0) {
        unsigned old = atomicAdd(&g_cnt, 1u);
        slast = (old == GRID_MAIN - 1) ? 1 : 0;
    }
    __syncthreads();
    if (slast && threadIdx.x < 128) {
        const int t = threadIdx.x;
        const double inv = 1.0 / (double)ROWS;
        if (t < 64) {
            const double sum = atomicAdd(&g_stats[t], 0.0);
            const double sq  = atomicAdd(&g_stats[64 + t], 0.0);
            const double mean = sum * inv;
            const double var  = sq * inv - mean * mean;
            const float a = g1[t] * rsqrtf((float)var + BN_EPS);
            g_aff[t]      = a;
            g_aff[64 + t] = be1[t] - (float)mean * a;
        } else {
            const int c = t - 64;
            const double sum = atomicAdd(&g_stats[128 + c], 0.0);
            const double sq  = atomicAdd(&g_stats[192 + c], 0.0);
            const double mean = sum * inv;
            const double var  = sq * inv - mean * mean;
            const float a = g2[c] * rsqrtf((float)var + BN_EPS);
            g_aff[128 + c] = a;
            g_aff[192 + c] = be2[c] - (float)mean * a;
        }
    }
}

// ---------------- epilogue: warp per row, 4 rows per warp ----------------
__global__ void __launch_bounds__(256)
k_epilogue(const float* __restrict__ skip_coords, float* __restrict__ out) {
    const int lane = threadIdx.x & 31;
    const int warp = threadIdx.x >> 5;
    const int r0 = (blockIdx.x * 8 + warp) * 4;
    const float2 a1 = ((const float2*)g_aff)[lane];
    const float2 d1 = ((const float2*)g_aff)[32 + lane];
    const float2 a2 = ((const float2*)g_aff)[64 + lane];
    const float2 d2 = ((const float2*)g_aff)[96 + lane];
#pragma unroll
    for (int r = 0; r < 4; ++r) {
        const int row = r0 + r;
        const float2 y1 = ((const float2*)g_y1)[(size_t)row * 32 + lane];
        const float2 y2 = ((const float2*)g_y2)[(size_t)row * 32 + lane];
        float* ob = out + (size_t)row * OUTC;
        if (lane < 3) ob[lane] = skip_coords[(size_t)row * 3 + lane];
        ob[3 + 2 * lane]  = fmaxf(fmaf(y1.x, a1.x, d1.x), 0.f);
        ob[4 + 2 * lane]  = fmaxf(fmaf(y1.y, a1.y, d1.y), 0.f);
        ob[67 + 2 * lane] = fmaxf(fmaf(y2.x, a2.x, d2.x), 0.f);
        ob[68 + 2 * lane] = fmaxf(fmaf(y2.y, a2.y, d2.y), 0.f);
    }
}

// ---------------- launch ----------------
extern "C" void kernel_launch(void* const* d_in, const int* in_sizes, int n_in,
                              void* d_out, int out_size) {
    // 0 curr_coords (unused), 1 curr_feat, 2 skip_coords, 3 skip_feat,
    // 4 upsampling_idxs, 5 W1, 6 b1, 7 g1, 8 beta1, 9 W2, 10 b2, 11 g2, 12 beta2
    const float* curr_feat   = (const float*)d_in[1];
    const float* skip_coords = (const float*)d_in[2];
    const float* skip_feat   = (const float*)d_in[3];
    const int*   idx         = (const int*)d_in[4];
    const float* W1  = (const float*)d_in[5];
    const float* b1  = (const float*)d_in[6];
    const float* g1  = (const float*)d_in[7];
    const float* be1 = (const float*)d_in[8];
    const float* W2  = (const float*)d_in[9];
    const float* b2  = (const float*)d_in[10];
    const float* g2  = (const float*)d_in[11];
    const float* be2 = (const float*)d_in[12];
    float* out = (float*)d_out;

    cudaFuncSetAttribute(k_main, cudaFuncAttributeMaxDynamicSharedMemorySize, SMEM_BYTES);

    k_pre<<<64, 256>>>(idx);
    k_main<<<GRID_MAIN, 256, SMEM_BYTES>>>(curr_feat, skip_feat, idx,
                                           W1, b1, W2, b2, g1, be1, g2, be2);
    k_epilogue<<<ROWS / 32, 256>>>(skip_coords, out);
}

// round 11
// speedup vs baseline: 1.2162x; 1.0637x over previous
#include <cuda_runtime.h>
#include <math.h>
#include <stdint.h>

typedef unsigned long long u64;

#define BATCH 4
#define MPTS  16384
#define NPTS  32768
#define KNN   16
#define CH    64
#define ROWS  (BATCH*NPTS)     // 131072
#define OUTC  131
#define BN_EPS 1e-5f

#define WARPS 8
#define PAIRS 16               // row-pairs per warp
#define RPW   (2*PAIRS)        // 32 rows per warp
#define RPB   (WARPS*RPW)      // 256 rows per block
#define GRID_MAIN (ROWS/RPB)   // 512

// dynamic smem: sW (4096 u64, W duplicated), sx (8 warps * 1024 u64), sred (256 f32)
#define SMEM_BYTES ((4096 + 8192) * 8 + 256 * 4)

#define EROWS 32               // rows per epilogue block

// ---------------- scratch (static device memory; no allocation) --------------
__device__ float  g_y1[(size_t)ROWS * CH];
__device__ float  g_y2[(size_t)ROWS * CH];
__device__ double g_stats[256];      // [sum1|sq1|sum2|sq2] x 64 ch  (zero-init; reset by finalize)
__device__ float  g_aff[256];        // [a1|d1|a2|d2] x 64 ch
__device__ unsigned int g_cnt;       // last-block counter (reset by finalize)

// ---------------- packed f32x2 helpers ----------------
__device__ __forceinline__ u64 pk(float lo, float hi) {
    u64 r; asm("mov.b64 %0,{%1,%2};" : "=l"(r) : "f"(lo), "f"(hi)); return r;
}
__device__ __forceinline__ void upk(u64 v, float& lo, float& hi) {
    asm("mov.b64 {%0,%1},%2;" : "=f"(lo), "=f"(hi) : "l"(v));
}
__device__ __forceinline__ void fma2(u64& d, u64 a, u64 b) {
    asm("fma.rn.f32x2 %0,%1,%2,%0;" : "+l"(d) : "l"(a), "l"(b));
}
__device__ __forceinline__ void add2(u64& d, u64 a) {
    asm("add.rn.f32x2 %0,%0,%1;" : "+l"(d) : "l"(a));
}

// ---------------- streaming (evict-first) memory helpers ----------------
__device__ __forceinline__ void stcs2(float* p, float2 v) {
    asm volatile("st.global.cs.v2.f32 [%0],{%1,%2};" :: "l"(p), "f"(v.x), "f"(v.y) : "memory");
}
__device__ __forceinline__ float2 ldcs2(const float* p) {
    float2 v;
    asm volatile("ld.global.cs.v2.f32 {%0,%1},[%2];" : "=f"(v.x), "=f"(v.y) : "l"(p));
    return v;
}
__device__ __forceinline__ void stcs4(float* p, float4 v) {
    asm volatile("st.global.cs.v4.f32 [%0],{%1,%2,%3,%4};"
                 :: "l"(p), "f"(v.x), "f"(v.y), "f"(v.z), "f"(v.w) : "memory");
}

// ---------------- gather one row: KNN max-pool, lane owns ch (2l, 2l+1) ------
__device__ __forceinline__ float2 gather_row(const float2* __restrict__ cf,
                                             const int* __restrict__ idx,
                                             int row, int lane, bool is64) {
    const float2* fb = cf + (size_t)(row >> 15) * (MPTS * 32);
    int myidx = 0;
    if (lane < KNN) {
        const int off = row * KNN + lane;
        myidx = is64 ? idx[2 * off] : idx[off];
    }
    float2 m = make_float2(-3.0e38f, -3.0e38f);
#pragma unroll
    for (int k = 0; k < KNN; ++k) {
        const int id = __shfl_sync(0xffffffffu, myidx, k);
        const float2 v = __ldg(&fb[(size_t)id * 32 + lane]);
        m.x = fmaxf(m.x, v.x);
        m.y = fmaxf(m.y, v.y);
    }
    return m;
}

// ---------------- packed-pair GEMM: acc over 16 row-pairs, 2 channels --------
__device__ __forceinline__ void gemm_pairs(const u64* __restrict__ sW,
                                           const u64* __restrict__ sxw,
                                           u64* acc0, u64* acc1, int l2) {
#pragma unroll 1
    for (int k = 0; k < 64; k += 2) {
        ulonglong2 wA = *(const ulonglong2*)(sW + k * 64 + l2);        // dup W[k][c0],W[k][c1]
        ulonglong2 wB = *(const ulonglong2*)(sW + (k + 1) * 64 + l2);
#pragma unroll
        for (int p = 0; p < PAIRS; ++p) {
            ulonglong2 xq = *(const ulonglong2*)(sxw + p * 64 + k);    // x pair k, pair k+1
            fma2(acc0[p], xq.x, wA.x);
            fma2(acc1[p], xq.x, wA.y);
            fma2(acc0[p], xq.y, wB.x);
            fma2(acc1[p], xq.y, wB.y);
        }
    }
}

// ---------------- main fused kernel ----------------
__global__ void __launch_bounds__(256, 2)
k_main(const float* __restrict__ curr_feat,
       const float* __restrict__ skip_feat,
       const int*   __restrict__ idx,
       const float* __restrict__ W1, const float* __restrict__ b1,
       const float* __restrict__ W2, const float* __restrict__ b2,
       const float* __restrict__ g1, const float* __restrict__ be1,
       const float* __restrict__ g2, const float* __restrict__ be2) {
    extern __shared__ u64 dsm[];
    u64*   sW   = dsm;                 // 4096 u64
    u64*   sx   = dsm + 4096;          // 8192 u64
    float* sred = (float*)(dsm + 4096 + 8192);
    __shared__ int slast;

    const int lane = threadIdx.x & 31;
    const int warp = threadIdx.x >> 5;
    const int l2   = 2 * lane;
    const int base = (blockIdx.x * WARPS + warp) * RPW;
    u64* sxw = sx + warp * (PAIRS * 64);

    // in-warp idx dtype detect: odd int32 words of the first 64 words are the
    // high halves of entries 0..31 iff int64 (all zero, indices < 16384).
    // In-bounds and L1/L2-hot under either dtype. Deterministic.
    const bool is64 = (__ballot_sync(0xffffffffu, idx[2 * lane + 1] != 0) == 0u);

    // stage W1 duplicated + zero sred
    for (int t = threadIdx.x; t < 4096; t += 256) { float w = W1[t]; sW[t] = pk(w, w); }
    sred[threadIdx.x] = 0.f;

    // gather + max-pool + pack row pairs into smem
#pragma unroll 1
    for (int p = 0; p < PAIRS; ++p) {
        float2 xa = gather_row((const float2*)curr_feat, idx, base + 2 * p,     lane, is64);
        float2 xb = gather_row((const float2*)curr_feat, idx, base + 2 * p + 1, lane, is64);
        ulonglong2 pr; pr.x = pk(xa.x, xb.x); pr.y = pk(xa.y, xb.y);
        *(ulonglong2*)(sxw + p * 64 + l2) = pr;
    }
    __syncthreads();   // W1 staged + own x visible

    // ---- GEMM1 ----
    u64 acc0[PAIRS], acc1[PAIRS];
    {
        float2 bb = ((const float2*)b1)[lane];
        u64 c0 = pk(bb.x, bb.x), c1 = pk(bb.y, bb.y);
#pragma unroll
        for (int p = 0; p < PAIRS; ++p) { acc0[p] = c0; acc1[p] = c1; }
    }
    gemm_pairs(sW, sxw, acc0, acc1, l2);

    // stats + store y1 (streaming, keep curr_feat L2-resident)
    {
        u64 s0 = 0, s1 = 0, q0 = 0, q1 = 0;
#pragma unroll
        for (int p = 0; p < PAIRS; ++p) {
            add2(s0, acc0[p]); add2(s1, acc1[p]);
            fma2(q0, acc0[p], acc0[p]); fma2(q1, acc1[p], acc1[p]);
            float aLo, aHi, bLo, bHi;
            upk(acc0[p], aLo, aHi); upk(acc1[p], bLo, bHi);
            stcs2(g_y1 + ((size_t)(base + 2 * p) * 32 + lane) * 2,     make_float2(aLo, bLo));
            stcs2(g_y1 + ((size_t)(base + 2 * p + 1) * 32 + lane) * 2, make_float2(aHi, bHi));
        }
        float lo, hi;
        upk(s0, lo, hi); atomicAdd(&sred[l2],          lo + hi);
        upk(s1, lo, hi); atomicAdd(&sred[l2 + 1],      lo + hi);
        upk(q0, lo, hi); atomicAdd(&sred[64 + l2],     lo + hi);
        upk(q1, lo, hi); atomicAdd(&sred[64 + l2 + 1], lo + hi);
    }
    __syncthreads();   // everyone done reading W1

    // stage W2 + pack skip_feat pairs (streaming reads: no reuse)
    for (int t = threadIdx.x; t < 4096; t += 256) { float w = W2[t]; sW[t] = pk(w, w); }
#pragma unroll 1
    for (int p = 0; p < PAIRS; ++p) {
        float2 xa = ldcs2(skip_feat + ((size_t)(base + 2 * p) * 32 + lane) * 2);
        float2 xb = ldcs2(skip_feat + ((size_t)(base + 2 * p + 1) * 32 + lane) * 2);
        ulonglong2 pr; pr.x = pk(xa.x, xb.x); pr.y = pk(xa.y, xb.y);
        *(ulonglong2*)(sxw + p * 64 + l2) = pr;
    }
    __syncthreads();

    // ---- GEMM2 ----
    {
        float2 bb = ((const float2*)b2)[lane];
        u64 c0 = pk(bb.x, bb.x), c1 = pk(bb.y, bb.y);
#pragma unroll
        for (int p = 0; p < PAIRS; ++p) { acc0[p] = c0; acc1[p] = c1; }
    }
    gemm_pairs(sW, sxw, acc0, acc1, l2);

    {
        u64 s0 = 0, s1 = 0, q0 = 0, q1 = 0;
#pragma unroll
        for (int p = 0; p < PAIRS; ++p) {
            add2(s0, acc0[p]); add2(s1, acc1[p]);
            fma2(q0, acc0[p], acc0[p]); fma2(q1, acc1[p], acc1[p]);
            float aLo, aHi, bLo, bHi;
            upk(acc0[p], aLo, aHi); upk(acc1[p], bLo, bHi);
            stcs2(g_y2 + ((size_t)(base + 2 * p) * 32 + lane) * 2,     make_float2(aLo, bLo));
            stcs2(g_y2 + ((size_t)(base + 2 * p + 1) * 32 + lane) * 2, make_float2(aHi, bHi));
        }
        float lo, hi;
        upk(s0, lo, hi); atomicAdd(&sred[128 + l2],     lo + hi);
        upk(s1, lo, hi); atomicAdd(&sred[128 + l2 + 1], lo + hi);
        upk(q0, lo, hi); atomicAdd(&sred[192 + l2],     lo + hi);
        upk(q1, lo, hi); atomicAdd(&sred[192 + l2 + 1], lo + hi);
    }
    __syncthreads();

    // global stats + last-block inline finalize (also resets scratch for graph replay)
    atomicAdd(&g_stats[threadIdx.x], (double)sred[threadIdx.x]);
    __threadfence();
    __syncthreads();
    if (threadIdx.x == 0) {
        unsigned old = atomicAdd(&g_cnt, 1u);
        slast = (old == GRID_MAIN - 1) ? 1 : 0;
    }
    __syncthreads();
    if (slast && threadIdx.x < 128) {
        const int t = threadIdx.x;
        const double inv = 1.0 / (double)ROWS;
        if (t < 64) {
            const double sum = atomicAdd(&g_stats[t], 0.0);
            const double sq  = atomicAdd(&g_stats[64 + t], 0.0);
            const double mean = sum * inv;
            const double var  = sq * inv - mean * mean;
            const float a = g1[t] * rsqrtf((float)var + BN_EPS);
            g_aff[t]      = a;
            g_aff[64 + t] = be1[t] - (float)mean * a;
            g_stats[t] = 0.0; g_stats[64 + t] = 0.0;
        } else {
            const int c = t - 64;
            const double sum = atomicAdd(&g_stats[128 + c], 0.0);
            const double sq  = atomicAdd(&g_stats[192 + c], 0.0);
            const double mean = sum * inv;
            const double var  = sq * inv - mean * mean;
            const float a = g2[c] * rsqrtf((float)var + BN_EPS);
            g_aff[128 + c] = a;
            g_aff[192 + c] = be2[c] - (float)mean * a;
            g_stats[128 + c] = 0.0; g_stats[192 + c] = 0.0;
        }
        if (t == 0) g_cnt = 0u;
    }
}

// ---------------- epilogue: smem-staged, fully coalesced float4 stores -------
__global__ void __launch_bounds__(256)
k_epilogue(const float* __restrict__ skip_coords, float* __restrict__ out) {
    __shared__ float srow[EROWS * OUTC];   // 4192 floats = 16.7 KB
    const int lane = threadIdx.x & 31;
    const int warp = threadIdx.x >> 5;
    const int r0 = blockIdx.x * EROWS + warp * 4;
    const float2 a1 = ((const float2*)g_aff)[lane];
    const float2 d1 = ((const float2*)g_aff)[32 + lane];
    const float2 a2 = ((const float2*)g_aff)[64 + lane];
    const float2 d2 = ((const float2*)g_aff)[96 + lane];
#pragma unroll
    for (int r = 0; r < 4; ++r) {
        const int row = r0 + r;
        const float2 y1 = ldcs2(g_y1 + ((size_t)row * 32 + lane) * 2);
        const float2 y2 = ldcs2(g_y2 + ((size_t)row * 32 + lane) * 2);
        float* sb = srow + (warp * 4 + r) * OUTC;
        if (lane < 3) sb[lane] = skip_coords[(size_t)row * 3 + lane];
        sb[3 + 2 * lane]  = fmaxf(fmaf(y1.x, a1.x, d1.x), 0.f);
        sb[4 + 2 * lane]  = fmaxf(fmaf(y1.y, a1.y, d1.y), 0.f);
        sb[67 + 2 * lane] = fmaxf(fmaf(y2.x, a2.x, d2.x), 0.f);
        sb[68 + 2 * lane] = fmaxf(fmaf(y2.y, a2.y, d2.y), 0.f);
    }
    __syncthreads();
    // flat, 16B-aligned, coalesced streaming writes: 1048 float4 per block
    float* ob = out + (size_t)blockIdx.x * (EROWS * OUTC);
    const float4* s4 = (const float4*)srow;
#pragma unroll
    for (int i = threadIdx.x; i < EROWS * OUTC / 4; i += 256)
        stcs4(ob + 4 * i, s4[i]);
}

// ---------------- launch ----------------
extern "C" void kernel_launch(void* const* d_in, const int* in_sizes, int n_in,
                              void* d_out, int out_size) {
    // 0 curr_coords (unused), 1 curr_feat, 2 skip_coords, 3 skip_feat,
    // 4 upsampling_idxs, 5 W1, 6 b1, 7 g1, 8 beta1, 9 W2, 10 b2, 11 g2, 12 beta2
    const float* curr_feat   = (const float*)d_in[1];
    const float* skip_coords = (const float*)d_in[2];
    const float* skip_feat   = (const float*)d_in[3];
    const int*   idx         = (const int*)d_in[4];
    const float* W1  = (const float*)d_in[5];
    const float* b1  = (const float*)d_in[6];
    const float* g1  = (const float*)d_in[7];
    const float* be1 = (const float*)d_in[8];
    const float* W2  = (const float*)d_in[9];
    const float* b2  = (const float*)d_in[10];
    const float* g2  = (const float*)d_in[11];
    const float* be2 = (const float*)d_in[12];
    float* out = (float*)d_out;

    cudaFuncSetAttribute(k_main, cudaFuncAttributeMaxDynamicSharedMemorySize, SMEM_BYTES);

    k_main<<<GRID_MAIN, 256, SMEM_BYTES>>>(curr_feat, skip_feat, idx,
                                           W1, b1, W2, b2, g1, be1, g2, be2);
    k_epilogue<<<ROWS / EROWS, 256>>>(skip_coords, out);
}